// round 13
// baseline (speedup 1.0000x reference)
#include <cuda_runtime.h>
#include <cstdint>

// ---------------------------------------------------------------------------
// Problem dims
// ---------------------------------------------------------------------------
#define T_STEPS 256
#define BATCH   128
#define N_INP   784
#define N_HID   512
#define N_OUT   128
#define M_TOTAL (T_STEPS * BATCH)   // 32768
#define L1STRIDE 160                // u32 offset slots per input list row (40 uint4 groups)
#define L2STRIDE 544                // u32 offset slots per hidden list row (136 groups)
#define HWORDS   16                 // 512/32 hidden-mask words per row
#define PADOFF1  (N_INP * 128)      // byte offset of zero row in F1 slab (32 floats/row)
#define PADOFF2  (N_HID * 128)      // byte offset of zero row in F2 slab

// ---------------------------------------------------------------------------
// Scratch globals
// ---------------------------------------------------------------------------
__device__ __align__(128) float    g_wt1[N_INP * N_HID];                // w_hidden^T
__device__ __align__(128) float    g_wt2[N_HID * N_OUT];                // w_out^T
__device__ __align__(128) uint32_t g_list1[(size_t)M_TOTAL * L1STRIDE]; // 21 MB
__device__ __align__(128) int      g_cnt1[M_TOTAL];
__device__ __align__(128) uint32_t g_shb[(size_t)M_TOTAL * HWORDS];     // 2 MB
__device__ __align__(128) uint32_t g_list2[(size_t)M_TOTAL * L2STRIDE]; // 71 MB
__device__ __align__(128) int      g_cnt2[M_TOTAL];
__device__ __align__(128) float    g_co[(size_t)M_TOTAL * N_OUT];       // 16 MB

// ---------------------------------------------------------------------------
// Weight transposes
// ---------------------------------------------------------------------------
__global__ void prep_wt1_kernel(const float* __restrict__ wh, float* __restrict__ wt1)
{
    int idx = blockIdx.x * blockDim.x + threadIdx.x;     // k*512 + u
    if (idx >= N_INP * N_HID) return;
    int k = idx >> 9, u = idx & 511;
    wt1[idx] = __ldg(wh + (size_t)u * N_INP + k);
}

__global__ void prep_wt2_kernel(const float* __restrict__ wo, float* __restrict__ wt2)
{
    int idx = blockIdx.x * blockDim.x + threadIdx.x;     // k*128 + o
    if (idx >= N_HID * N_OUT) return;
    int k = idx >> 7, o = idx & 127;
    wt2[idx] = __ldg(wo + (size_t)o * N_HID + k);
}

// ---------------------------------------------------------------------------
// Build input active lists as PRE-SCALED u32 byte offsets (k*128).
// One warp per row; fully pads the row with the zero-row offset.
// ---------------------------------------------------------------------------
__global__ void build_list1_kernel(const float* __restrict__ sp,
                                   uint32_t* __restrict__ list, int* __restrict__ cnts)
{
    const int wid  = threadIdx.x >> 5;
    const int lane = threadIdx.x & 31;
    const int row  = blockIdx.x * 8 + wid;

    uint32_t w = 0;
    if (lane < 24) {
        const float4* p = (const float4*)(sp + (size_t)row * N_INP + lane * 32);
#pragma unroll
        for (int j = 0; j < 8; j++) {
            float4 f = p[j];
            w |= (uint32_t)(f.x > 0.5f) << (j * 4 + 0);
            w |= (uint32_t)(f.y > 0.5f) << (j * 4 + 1);
            w |= (uint32_t)(f.z > 0.5f) << (j * 4 + 2);
            w |= (uint32_t)(f.w > 0.5f) << (j * 4 + 3);
        }
    } else if (lane == 24) {
        const float4* p = (const float4*)(sp + (size_t)row * N_INP + 768);
#pragma unroll
        for (int j = 0; j < 4; j++) {                    // inputs 768..783
            float4 f = p[j];
            w |= (uint32_t)(f.x > 0.5f) << (j * 4 + 0);
            w |= (uint32_t)(f.y > 0.5f) << (j * 4 + 1);
            w |= (uint32_t)(f.z > 0.5f) << (j * 4 + 2);
            w |= (uint32_t)(f.w > 0.5f) << (j * 4 + 3);
        }
    }

    int c = __popc(w);
    int incl = c;
#pragma unroll
    for (int d = 1; d < 32; d <<= 1) {
        int n = __shfl_up_sync(0xffffffffu, incl, d);
        if (lane >= d) incl += n;
    }
    int total = __shfl_sync(0xffffffffu, incl, 31);
    if (total > L1STRIDE - 16) total = L1STRIDE - 16;    // safety clamp (never hit)
    int p0 = incl - c;

    uint32_t* lp = list + (size_t)row * L1STRIDE;
    uint32_t m = w;
    int kb = lane * 32;
    while (m) {
        int k = kb + __ffs(m) - 1;
        m &= m - 1;
        if (p0 < L1STRIDE - 16) lp[p0] = (uint32_t)(k * 128);
        p0++;
    }
    for (int i = total + lane; i < L1STRIDE; i += 32)
        lp[i] = (uint32_t)PADOFF1;                       // pad -> zero weight row
    if (lane == 0) cnts[row] = total;
}

// ---------------------------------------------------------------------------
// Build hidden active lists (pre-scaled u32 offsets) from ballot bitmask.
// ---------------------------------------------------------------------------
__global__ void build_list2_kernel(const uint32_t* __restrict__ mask,
                                   uint32_t* __restrict__ list, int* __restrict__ cnts)
{
    const int wid  = threadIdx.x >> 5;
    const int lane = threadIdx.x & 31;
    const int row  = blockIdx.x * 8 + wid;

    uint32_t w = (lane < HWORDS) ? mask[(size_t)row * HWORDS + lane] : 0u;
    int c = __popc(w);
    int incl = c;
#pragma unroll
    for (int d = 1; d < 32; d <<= 1) {
        int n = __shfl_up_sync(0xffffffffu, incl, d);
        if (lane >= d) incl += n;
    }
    int total = __shfl_sync(0xffffffffu, incl, 31);      // <= 512
    int p0 = incl - c;

    uint32_t* lp = list + (size_t)row * L2STRIDE;
    uint32_t m = w;
    int kb = lane * 32;
    while (m) {
        int k = kb + __ffs(m) - 1;
        m &= m - 1;
        lp[p0++] = (uint32_t)(k * 128);
    }
    for (int i = total + lane; i < L2STRIDE; i += 32)
        lp[i] = (uint32_t)PADOFF2;
    if (lane == 0) cnts[row] = total;
}

// 4 scalar accumulations from one uint4 of pre-scaled offsets
#define ACC4(U, A)                                        \
    { A += *(const float*)(swb + U.x);                    \
      A += *(const float*)(swb + U.y);                    \
      A += *(const float*)(swb + U.z);                    \
      A += *(const float*)(swb + U.w); }

// ---------------------------------------------------------------------------
// F1: fused sparse GEMM1 + LIF, 8 timesteps interleaved, 32-unit chunks.
// Grid (16 chunks, 16 btiles of 8 warps) = 256 CTAs; slab float[785][32]
// = 100480 B -> 2 CTAs/SM. Warp = batch; lane owns unit ub+lane.
// ---------------------------------------------------------------------------
__global__ __launch_bounds__(256, 2)
void f1_kernel(const float* __restrict__ wt1, const uint32_t* __restrict__ list,
               const int* __restrict__ cnts, uint32_t* __restrict__ shb)
{
    extern __shared__ float sw[];                        // [785][32]
    const int tid   = threadIdx.x;
    const int wid   = tid >> 5;
    const int lane  = tid & 31;
    const int chunk = blockIdx.x;                        // 0..15
    const int ub    = chunk * 32;

    for (int i = tid; i < (N_INP + 1) * 32; i += 256) {
        int k = i >> 5, l = i & 31;
        sw[i] = (k < N_INP) ? wt1[(size_t)k * N_HID + ub + l] : 0.0f;
    }
    __syncthreads();

    const char* swb = (const char*)sw + lane * 4;        // lane-fixed slab base
    const int b = blockIdx.y * 8 + wid;
    const float Am = (float)(1e-6 * (1.0 / 6e-6));
    const float Cd = (float)(1.0 - 1e-6 * (1.0 / 6e-6));
    float v = 0.f, cur = 0.f;

    for (int t0 = 0; t0 < T_STEPS; t0 += 8) {
        const uint4* lp[8];
        int cmax = 0;
#pragma unroll
        for (int i = 0; i < 8; i++) {
            int row = (t0 + i) * BATCH + b;
            lp[i] = (const uint4*)(list + (size_t)row * L1STRIDE);
            int cc = cnts[row];
            cmax = cc > cmax ? cc : cmax;
        }
        int gmax = (cmax + 3) >> 2;                      // groups of 4

        uint4 q[8], nx[8];
        float a[8];
#pragma unroll
        for (int i = 0; i < 8; i++) { q[i] = lp[i][0]; nx[i] = lp[i][1]; a[i] = 0.f; }

        for (int j = 0; j < gmax; j++) {
            int g = j + 2;                               // <= 37 < 40 (full pad)
#pragma unroll
            for (int i = 0; i < 8; i++) {
                uint4 u = q[i];
                q[i] = nx[i];
                nx[i] = lp[i][g];
                ACC4(u, a[i]);
            }
        }

        // LIF: 8 sequential steps (reference op order)
#pragma unroll
        for (int i = 0; i < 8; i++) {
            v = v + Am * (cur - v);
            cur = cur * Cd + a[i];
            bool z = (v - 1.0f) > 0.0f;
            uint32_t bb = __ballot_sync(0xffffffffu, z);
            if (lane == 0)
                shb[((size_t)(t0 + i) * BATCH + b) * HWORDS + chunk] = bb;
            if (z) v = 0.0f;
        }
    }
}

// ---------------------------------------------------------------------------
// F2: sparse GEMM2, 8-t interleave, 32-out chunks, t-sliced x4.
// Grid x = chunk(4) + 4*tslice(4) = 16; y = 16 btiles of 8 warps = 256 CTAs.
// Slab float[513][32] = 65664 B -> 3 CTAs/SM.
// ---------------------------------------------------------------------------
__global__ __launch_bounds__(256, 2)
void f2_kernel(const float* __restrict__ wt2, const uint32_t* __restrict__ list,
               const int* __restrict__ cnts, float* __restrict__ co)
{
    extern __shared__ float sw[];                        // [513][32]
    const int tid   = threadIdx.x;
    const int wid   = tid >> 5;
    const int lane  = tid & 31;
    const int chunk = blockIdx.x & 3;                    // 0..3
    const int ts    = blockIdx.x >> 2;                   // 0..3
    const int ob    = chunk * 32;

    for (int i = tid; i < (N_HID + 1) * 32; i += 256) {
        int k = i >> 5, l = i & 31;
        sw[i] = (k < N_HID) ? wt2[(size_t)k * N_OUT + ob + l] : 0.0f;
    }
    __syncthreads();

    const char* swb = (const char*)sw + lane * 4;
    const int b   = blockIdx.y * 8 + wid;
    const int t0s = ts * (T_STEPS / 4);

    for (int t0 = t0s; t0 < t0s + T_STEPS / 4; t0 += 8) {
        const uint4* lp[8];
        int cmax = 0;
#pragma unroll
        for (int i = 0; i < 8; i++) {
            int row = (t0 + i) * BATCH + b;
            lp[i] = (const uint4*)(list + (size_t)row * L2STRIDE);
            int cc = cnts[row];
            cmax = cc > cmax ? cc : cmax;
        }
        int gmax = (cmax + 3) >> 2;

        uint4 q[8], nx[8];
        float a[8];
#pragma unroll
        for (int i = 0; i < 8; i++) { q[i] = lp[i][0]; nx[i] = lp[i][1]; a[i] = 0.f; }

        for (int j = 0; j < gmax; j++) {
            int g = j + 2;                               // <= 129 < 136 (full pad)
#pragma unroll
            for (int i = 0; i < 8; i++) {
                uint4 u = q[i];
                q[i] = nx[i];
                nx[i] = lp[i][g];
                ACC4(u, a[i]);
            }
        }

#pragma unroll
        for (int i = 0; i < 8; i++)
            co[((size_t)(t0 + i) * BATCH + b) * N_OUT + ob + lane] = a[i];
    }
}

// ---------------------------------------------------------------------------
// LI readout scan
// ---------------------------------------------------------------------------
__global__ void li_kernel(const float* __restrict__ co, float* __restrict__ out)
{
    const int tid = blockIdx.x * blockDim.x + threadIdx.x;   // b*128 + o
    const float Am = (float)(1e-6 * (1.0 / 6e-6));
    const float Cd = (float)(1.0 - 1e-6 * (1.0 / 6e-6));
    float v = 0.0f, cur = 0.0f;
    const int stride = BATCH * N_OUT;

    for (int t0 = 0; t0 < T_STEPS; t0 += 16) {
        float x[16];
#pragma unroll
        for (int u = 0; u < 16; u++)
            x[u] = co[(size_t)(t0 + u) * stride + tid];
#pragma unroll
        for (int u = 0; u < 16; u++) {
            v = v + Am * (cur - v);
            cur = cur * Cd + x[u];
            out[(size_t)(t0 + u) * stride + tid] = v;
        }
    }
}

// ---------------------------------------------------------------------------
// Launch
// ---------------------------------------------------------------------------
extern "C" void kernel_launch(void* const* d_in, const int* in_sizes, int n_in,
                              void* d_out, int out_size)
{
    const float* spikes = (const float*)d_in[0];
    const float* wh     = (const float*)d_in[1];
    const float* wo     = (const float*)d_in[2];
    float*       out    = (float*)d_out;

    float *wt1, *wt2, *co;
    uint32_t *l1, *l2, *shb;
    int *c1, *c2;
    cudaGetSymbolAddress((void**)&wt1, g_wt1);
    cudaGetSymbolAddress((void**)&wt2, g_wt2);
    cudaGetSymbolAddress((void**)&l1,  g_list1);
    cudaGetSymbolAddress((void**)&c1,  g_cnt1);
    cudaGetSymbolAddress((void**)&shb, g_shb);
    cudaGetSymbolAddress((void**)&l2,  g_list2);
    cudaGetSymbolAddress((void**)&c2,  g_cnt2);
    cudaGetSymbolAddress((void**)&co,  g_co);

    constexpr int SW1 = (N_INP + 1) * 32 * sizeof(float);    // 100480
    constexpr int SW2 = (N_HID + 1) * 32 * sizeof(float);    //  65664
    cudaFuncSetAttribute((const void*)f1_kernel, cudaFuncAttributeMaxDynamicSharedMemorySize, SW1);
    cudaFuncSetAttribute((const void*)f2_kernel, cudaFuncAttributeMaxDynamicSharedMemorySize, SW2);

    // preps
    prep_wt1_kernel<<<(N_INP * N_HID + 255) / 256, 256>>>(wh, wt1);
    prep_wt2_kernel<<<(N_HID * N_OUT + 255) / 256, 256>>>(wo, wt2);
    build_list1_kernel<<<M_TOTAL / 8, 256>>>(spikes, l1, c1);

    // fused sparse GEMM1 + LIF
    f1_kernel<<<dim3(16, 16), 256, SW1>>>(wt1, l1, c1, shb);

    // hidden lists + sparse GEMM2 (t-sliced)
    build_list2_kernel<<<M_TOTAL / 8, 256>>>(shb, l2, c2);
    f2_kernel<<<dim3(16, 16), 256, SW2>>>(wt2, l2, c2, co);

    // LI readout
    li_kernel<<<(BATCH * N_OUT) / 256, 256>>>(co, out);
}

// round 16
// speedup vs baseline: 1.0062x; 1.0062x over previous
#include <cuda_runtime.h>
#include <cstdint>

// ---------------------------------------------------------------------------
// Problem dims
// ---------------------------------------------------------------------------
#define T_STEPS 256
#define BATCH   128
#define N_HID   512
#define N_INP   784
#define N_OUT   128
#define M_TOTAL (T_STEPS * BATCH)   // 32768
#define HWORDS  16                  // 512/32 hidden-mask words per row

// F1 K-split: half0 = k<384 (12 mask words), half1 = k>=384 (400 inputs)
#define L1HALF   96                 // u32 slots per half (24 uint4 groups)
#define L1STRIDE (2 * L1HALF)
#define F1ROWS   401                // slab rows per half (400 + zero row)
#define PADOFF1  (400 * 256)        // zero-row byte offset (64 floats/row)

// F2 K-split: half0 = k<256, half1 = k>=256
#define L2HALF   272                // 256 max actives + 16 pad (68 groups)
#define L2STRIDE (2 * L2HALF)
#define F2ROWS   257
#define PADOFF2  (256 * 256)

typedef unsigned long long ull;

// ---------------------------------------------------------------------------
// Scratch globals
// ---------------------------------------------------------------------------
__device__ __align__(128) float    g_wt1[N_INP * N_HID];
__device__ __align__(128) float    g_wt2[N_HID * N_OUT];
__device__ __align__(128) uint32_t g_list1[(size_t)M_TOTAL * L1STRIDE]; // 25 MB
__device__ __align__(128) int2     g_cnt1[M_TOTAL];
__device__ __align__(128) uint32_t g_shb[(size_t)M_TOTAL * HWORDS];     // 2 MB
__device__ __align__(128) uint32_t g_list2[(size_t)M_TOTAL * L2STRIDE]; // 71 MB
__device__ __align__(128) int2     g_cnt2[M_TOTAL];
__device__ __align__(128) ull      g_chp0[(size_t)M_TOTAL * 256];       // 64 MB partial c_h (kh0)
__device__ __align__(128) ull      g_chp1[(size_t)M_TOTAL * 256];       // 64 MB partial c_h (kh1)
__device__ __align__(128) float    g_cop0[(size_t)M_TOTAL * N_OUT];     // 16 MB partial c_o
__device__ __align__(128) float    g_cop1[(size_t)M_TOTAL * N_OUT];     // 16 MB

// ---------------------------------------------------------------------------
// Weight transposes
// ---------------------------------------------------------------------------
__global__ void prep_wt1_kernel(const float* __restrict__ wh, float* __restrict__ wt1)
{
    int idx = blockIdx.x * blockDim.x + threadIdx.x;     // k*512 + u
    if (idx >= N_INP * N_HID) return;
    int k = idx >> 9, u = idx & 511;
    wt1[idx] = __ldg(wh + (size_t)u * N_INP + k);
}

__global__ void prep_wt2_kernel(const float* __restrict__ wo, float* __restrict__ wt2)
{
    int idx = blockIdx.x * blockDim.x + threadIdx.x;     // k*128 + o
    if (idx >= N_HID * N_OUT) return;
    int k = idx >> 7, o = idx & 127;
    wt2[idx] = __ldg(wo + (size_t)o * N_HID + k);
}

// ---------------------------------------------------------------------------
// Build input lists: per row, TWO k-half sublists of pre-scaled local byte
// offsets (k_local*256). Fully padded with the zero-row offset.
// ---------------------------------------------------------------------------
__global__ void build_list1_kernel(const float* __restrict__ sp,
                                   uint32_t* __restrict__ list, int2* __restrict__ cnts)
{
    const int wid  = threadIdx.x >> 5;
    const int lane = threadIdx.x & 31;
    const int row  = blockIdx.x * 8 + wid;

    uint32_t w = 0;
    if (lane < 24) {
        const float4* p = (const float4*)(sp + (size_t)row * N_INP + lane * 32);
#pragma unroll
        for (int j = 0; j < 8; j++) {
            float4 f = p[j];
            w |= (uint32_t)(f.x > 0.5f) << (j * 4 + 0);
            w |= (uint32_t)(f.y > 0.5f) << (j * 4 + 1);
            w |= (uint32_t)(f.z > 0.5f) << (j * 4 + 2);
            w |= (uint32_t)(f.w > 0.5f) << (j * 4 + 3);
        }
    } else if (lane == 24) {
        const float4* p = (const float4*)(sp + (size_t)row * N_INP + 768);
#pragma unroll
        for (int j = 0; j < 4; j++) {                    // inputs 768..783
            float4 f = p[j];
            w |= (uint32_t)(f.x > 0.5f) << (j * 4 + 0);
            w |= (uint32_t)(f.y > 0.5f) << (j * 4 + 1);
            w |= (uint32_t)(f.z > 0.5f) << (j * 4 + 2);
            w |= (uint32_t)(f.w > 0.5f) << (j * 4 + 3);
        }
    }

    int c = __popc(w);
    int incl = c;
#pragma unroll
    for (int d = 1; d < 32; d <<= 1) {
        int n = __shfl_up_sync(0xffffffffu, incl, d);
        if (lane >= d) incl += n;
    }
    int total  = __shfl_sync(0xffffffffu, incl, 31);
    int total0 = __shfl_sync(0xffffffffu, incl, 11);     // k<384 live in lanes 0..11
    int total1 = total - total0;

    uint32_t* lp   = list + (size_t)row * L1STRIDE;
    uint32_t* sub0 = lp;
    uint32_t* sub1 = lp + L1HALF;

    int kh   = (lane >= 12);
    int pos  = (incl - c) - (kh ? total0 : 0);
    int base = lane * 32 - (kh ? 384 : 0);               // local k within half
    uint32_t* dst = kh ? sub1 : sub0;
    uint32_t m = w;
    while (m) {
        int kl = base + __ffs(m) - 1;
        m &= m - 1;
        if (pos < L1HALF) dst[pos] = (uint32_t)(kl * 256);
        pos++;
    }
    if (total0 > L1HALF) total0 = L1HALF;
    if (total1 > L1HALF) total1 = L1HALF;
    for (int i = total0 + lane; i < L1HALF; i += 32) sub0[i] = (uint32_t)PADOFF1;
    for (int i = total1 + lane; i < L1HALF; i += 32) sub1[i] = (uint32_t)PADOFF1;
    if (lane == 0) cnts[row] = make_int2(total0, total1);
}

// ---------------------------------------------------------------------------
// Build hidden lists: per row, TWO k-half sublists (k<256 / k>=256).
// ---------------------------------------------------------------------------
__global__ void build_list2_kernel(const uint32_t* __restrict__ mask,
                                   uint32_t* __restrict__ list, int2* __restrict__ cnts)
{
    const int wid  = threadIdx.x >> 5;
    const int lane = threadIdx.x & 31;
    const int row  = blockIdx.x * 8 + wid;

    uint32_t w = (lane < HWORDS) ? mask[(size_t)row * HWORDS + lane] : 0u;
    int c = __popc(w);
    int incl = c;
#pragma unroll
    for (int d = 1; d < 32; d <<= 1) {
        int n = __shfl_up_sync(0xffffffffu, incl, d);
        if (lane >= d) incl += n;
    }
    int total  = __shfl_sync(0xffffffffu, incl, 31);
    int total0 = __shfl_sync(0xffffffffu, incl, 7);      // k<256 live in lanes 0..7
    int total1 = total - total0;

    uint32_t* lp   = list + (size_t)row * L2STRIDE;
    uint32_t* sub0 = lp;
    uint32_t* sub1 = lp + L2HALF;

    int kh   = (lane >= 8);
    int pos  = (incl - c) - (kh ? total0 : 0);
    int base = lane * 32 - (kh ? 256 : 0);
    uint32_t* dst = kh ? sub1 : sub0;
    uint32_t m = w;
    while (m) {
        int kl = base + __ffs(m) - 1;
        m &= m - 1;
        dst[pos++] = (uint32_t)(kl * 256);               // <= 256 fits in 272
    }
    for (int i = total0 + lane; i < L2HALF; i += 32) sub0[i] = (uint32_t)PADOFF2;
    for (int i = total1 + lane; i < L2HALF; i += 32) sub1[i] = (uint32_t)PADOFF2;
    if (lane == 0) cnts[row] = make_int2(total0, total1);
}

// Packed fp32x2 accumulate: ACC += slab[off + lane*8]
#define ACCO(OFF, ACC)                                                         \
    { ull w_ = *(const ull*)(swb + (OFF));                                     \
      asm("add.rn.f32x2 %0, %1, %2;" : "=l"(ACC) : "l"(ACC), "l"(w_)); }
#define ACC4(U, ACC)  { ACCO(U.x, ACC); ACCO(U.y, ACC); ACCO(U.z, ACC); ACCO(U.w, ACC); }

// ---------------------------------------------------------------------------
// F1a: sparse GEMM1 partials, 8-t interleave, 64-unit chunks, K-halved slab.
// Grid x = uchunk(8) + 8*khalf(2) = 16; y = 16 btiles of 8 warps = 256 CTAs.
// Slab float[401][64] = 102656 B -> 2 CTAs/SM. Lane owns units (ub+l, ub+32+l).
// Writes packed f32x2 partials: chp[row*256 + chunk*32 + lane].
// ---------------------------------------------------------------------------
__global__ __launch_bounds__(256, 2)
void f1a_kernel(const float* __restrict__ wt1, const uint32_t* __restrict__ list,
                const int2* __restrict__ cnts, ull* __restrict__ chp0,
                ull* __restrict__ chp1)
{
    extern __shared__ float sw[];                        // [401][64]
    const int tid   = threadIdx.x;
    const int wid   = tid >> 5;
    const int lane  = tid & 31;
    const int chunk = blockIdx.x & 7;
    const int kh    = blockIdx.x >> 3;
    const int ub    = chunk * 64;
    const int rows  = kh ? 400 : 384;                    // valid weight rows this half
    const int kbase = kh ? 384 : 0;

    for (int i = tid; i < F1ROWS * 64; i += 256) {
        int k = i >> 6, j = i & 63;
        int l = j >> 1, hi = j & 1;                      // slab[k][2l+hi] = w[k][ub+l+hi*32]
        sw[i] = (k < rows) ? wt1[(size_t)(kbase + k) * N_HID + ub + l + hi * 32] : 0.0f;
    }
    __syncthreads();

    const char* swb = (const char*)sw + lane * 8;
    const int b = blockIdx.y * 8 + wid;
    ull* __restrict__ chp = kh ? chp1 : chp0;

    for (int t0 = 0; t0 < T_STEPS; t0 += 8) {
        const uint4* lp[8];
        int cmax = 0;
#pragma unroll
        for (int i = 0; i < 8; i++) {
            int row = (t0 + i) * BATCH + b;
            lp[i] = (const uint4*)(list + (size_t)row * L1STRIDE + kh * L1HALF);
            int2 cc = cnts[row];
            int c = kh ? cc.y : cc.x;
            cmax = c > cmax ? c : cmax;
        }
        int gmax = (cmax + 3) >> 2;

        uint4 q[8], nx[8];
        ull acc[8];
#pragma unroll
        for (int i = 0; i < 8; i++) { q[i] = lp[i][0]; nx[i] = lp[i][1]; acc[i] = 0ull; }

        for (int j = 0; j < gmax; j++) {
            int g = j + 2;
            if (g > 23) g = 23;                          // clamp inside 24-group sublist
#pragma unroll
            for (int i = 0; i < 8; i++) {
                uint4 u = q[i];
                q[i] = nx[i];
                nx[i] = lp[i][g];
                ACC4(u, acc[i]);
            }
        }

#pragma unroll
        for (int i = 0; i < 8; i++)
            chp[((size_t)(t0 + i) * BATCH + b) * 256 + chunk * 32 + lane] = acc[i];
    }
}

// ---------------------------------------------------------------------------
// F1b: combine partials + LIF + ballot -> hidden bitmask.
// EXACTLY 32768 threads = 128 blocks x 256. Thread = (b, chunk, lane).
// ---------------------------------------------------------------------------
__global__ __launch_bounds__(256)
void f1b_kernel(const ull* __restrict__ chp0, const ull* __restrict__ chp1,
                uint32_t* __restrict__ shb)
{
    const int g     = blockIdx.x * 256 + threadIdx.x;    // 0..32767
    const int b     = g >> 8;                            // 0..127
    const int chunk = (g >> 5) & 7;
    const int lane  = g & 31;
    const int col   = chunk * 32 + lane;                 // ull column 0..255

    const float Am = (float)(1e-6 * (1.0 / 6e-6));
    const float Cd = (float)(1.0 - 1e-6 * (1.0 / 6e-6));
    float v0 = 0.f, c0 = 0.f, v1 = 0.f, c1 = 0.f;

    for (int t0 = 0; t0 < T_STEPS; t0 += 8) {
        float a0[8], a1[8];
#pragma unroll
        for (int i = 0; i < 8; i++) {
            size_t idx = ((size_t)(t0 + i) * BATCH + b) * 256 + col;
            ull p = chp0[idx], q = chp1[idx];
            a0[i] = __uint_as_float((uint32_t)(p & 0xffffffffu))
                  + __uint_as_float((uint32_t)(q & 0xffffffffu));
            a1[i] = __uint_as_float((uint32_t)(p >> 32))
                  + __uint_as_float((uint32_t)(q >> 32));
        }
#pragma unroll
        for (int i = 0; i < 8; i++) {
            v0 = v0 + Am * (c0 - v0);  c0 = c0 * Cd + a0[i];
            v1 = v1 + Am * (c1 - v1);  c1 = c1 * Cd + a1[i];
            bool z0 = (v0 - 1.0f) > 0.0f;
            bool z1 = (v1 - 1.0f) > 0.0f;
            uint32_t bb0 = __ballot_sync(0xffffffffu, z0);
            uint32_t bb1 = __ballot_sync(0xffffffffu, z1);
            size_t rb = ((size_t)(t0 + i) * BATCH + b) * HWORDS + chunk * 2;
            if (lane == 0) shb[rb]     = bb0;
            if (lane == 1) shb[rb + 1] = bb1;
            if (z0) v0 = 0.0f;
            if (z1) v1 = 0.0f;
        }
    }
}

// ---------------------------------------------------------------------------
// F2: sparse GEMM2 partials, 8-t interleave, K-halved slab, t-sliced x4.
// Grid x = ochunk(2) + 2*khalf(2) + 4*tslice(4) = 16; y = 16 btiles = 256 CTAs.
// Slab float[257][64] = 65792 B -> 2 CTAs/SM.
// ---------------------------------------------------------------------------
__global__ __launch_bounds__(256, 2)
void f2_kernel(const float* __restrict__ wt2, const uint32_t* __restrict__ list,
               const int2* __restrict__ cnts, float* __restrict__ cop0,
               float* __restrict__ cop1)
{
    extern __shared__ float sw[];                        // [257][64]
    const int tid    = threadIdx.x;
    const int wid    = tid >> 5;
    const int lane   = tid & 31;
    const int ochunk = blockIdx.x & 1;
    const int kh     = (blockIdx.x >> 1) & 1;
    const int ts     = blockIdx.x >> 2;
    const int ob     = ochunk * 64;
    const int kbase  = kh * 256;

    for (int i = tid; i < F2ROWS * 64; i += 256) {
        int k = i >> 6, j = i & 63;
        int l = j >> 1, hi = j & 1;
        sw[i] = (k < 256) ? wt2[(size_t)(kbase + k) * N_OUT + ob + l + hi * 32] : 0.0f;
    }
    __syncthreads();

    const char* swb = (const char*)sw + lane * 8;
    const int b   = blockIdx.y * 8 + wid;
    const int t0s = ts * (T_STEPS / 4);
    float* __restrict__ cop = kh ? cop1 : cop0;

    for (int t0 = t0s; t0 < t0s + T_STEPS / 4; t0 += 8) {
        const uint4* lp[8];
        int cmax = 0;
#pragma unroll
        for (int i = 0; i < 8; i++) {
            int row = (t0 + i) * BATCH + b;
            lp[i] = (const uint4*)(list + (size_t)row * L2STRIDE + kh * L2HALF);
            int2 cc = cnts[row];
            int c = kh ? cc.y : cc.x;
            cmax = c > cmax ? c : cmax;
        }
        int gmax = (cmax + 3) >> 2;                      // <= 64

        uint4 q[8], nx[8];
        ull acc[8];
#pragma unroll
        for (int i = 0; i < 8; i++) { q[i] = lp[i][0]; nx[i] = lp[i][1]; acc[i] = 0ull; }

        for (int j = 0; j < gmax; j++) {
            int g = j + 2;
            if (g > 67) g = 67;                          // clamp inside 68-group sublist
#pragma unroll
            for (int i = 0; i < 8; i++) {
                uint4 u = q[i];
                q[i] = nx[i];
                nx[i] = lp[i][g];
                ACC4(u, acc[i]);
            }
        }

#pragma unroll
        for (int i = 0; i < 8; i++) {
            size_t o = ((size_t)(t0 + i) * BATCH + b) * N_OUT + ob;
            cop[o + lane]      = __uint_as_float((uint32_t)(acc[i] & 0xffffffffu));
            cop[o + 32 + lane] = __uint_as_float((uint32_t)(acc[i] >> 32));
        }
    }
}

// ---------------------------------------------------------------------------
// LI readout scan over summed partials
// ---------------------------------------------------------------------------
__global__ void li_kernel(const float* __restrict__ cop0, const float* __restrict__ cop1,
                          float* __restrict__ out)
{
    const int tid = blockIdx.x * blockDim.x + threadIdx.x;   // b*128 + o
    const float Am = (float)(1e-6 * (1.0 / 6e-6));
    const float Cd = (float)(1.0 - 1e-6 * (1.0 / 6e-6));
    float v = 0.0f, cur = 0.0f;
    const int stride = BATCH * N_OUT;

    for (int t0 = 0; t0 < T_STEPS; t0 += 16) {
        float x[16];
#pragma unroll
        for (int u = 0; u < 16; u++) {
            size_t idx = (size_t)(t0 + u) * stride + tid;
            x[u] = cop0[idx] + cop1[idx];
        }
#pragma unroll
        for (int u = 0; u < 16; u++) {
            v = v + Am * (cur - v);
            cur = cur * Cd + x[u];
            out[(size_t)(t0 + u) * stride + tid] = v;
        }
    }
}

// ---------------------------------------------------------------------------
// Launch
// ---------------------------------------------------------------------------
extern "C" void kernel_launch(void* const* d_in, const int* in_sizes, int n_in,
                              void* d_out, int out_size)
{
    const float* spikes = (const float*)d_in[0];
    const float* wh     = (const float*)d_in[1];
    const float* wo     = (const float*)d_in[2];
    float*       out    = (float*)d_out;

    float *wt1, *wt2, *cop0, *cop1;
    uint32_t *l1, *l2, *shb;
    int2 *c1, *c2;
    ull *chp0, *chp1;
    cudaGetSymbolAddress((void**)&wt1,  g_wt1);
    cudaGetSymbolAddress((void**)&wt2,  g_wt2);
    cudaGetSymbolAddress((void**)&l1,   g_list1);
    cudaGetSymbolAddress((void**)&c1,   g_cnt1);
    cudaGetSymbolAddress((void**)&shb,  g_shb);
    cudaGetSymbolAddress((void**)&l2,   g_list2);
    cudaGetSymbolAddress((void**)&c2,   g_cnt2);
    cudaGetSymbolAddress((void**)&chp0, g_chp0);
    cudaGetSymbolAddress((void**)&chp1, g_chp1);
    cudaGetSymbolAddress((void**)&cop0, g_cop0);
    cudaGetSymbolAddress((void**)&cop1, g_cop1);

    constexpr int SW1 = F1ROWS * 64 * sizeof(float);     // 102656
    constexpr int SW2 = F2ROWS * 64 * sizeof(float);     //  65792
    cudaFuncSetAttribute((const void*)f1a_kernel, cudaFuncAttributeMaxDynamicSharedMemorySize, SW1);
    cudaFuncSetAttribute((const void*)f2_kernel,  cudaFuncAttributeMaxDynamicSharedMemorySize, SW2);

    // preps
    prep_wt1_kernel<<<(N_INP * N_HID + 255) / 256, 256>>>(wh, wt1);
    prep_wt2_kernel<<<(N_HID * N_OUT + 255) / 256, 256>>>(wo, wt2);
    build_list1_kernel<<<M_TOTAL / 8, 256>>>(spikes, l1, c1);

    // sparse GEMM1 partials (2 CTAs/SM), then combine + LIF + ballot
    f1a_kernel<<<dim3(16, 16), 256, SW1>>>(wt1, l1, c1, chp0, chp1);
    f1b_kernel<<<(BATCH * 8 * 32) / 256, 256>>>(chp0, chp1, shb);   // 128 blocks = 32768 threads

    // hidden lists + sparse GEMM2 partials (t-sliced, K-halved)
    build_list2_kernel<<<M_TOTAL / 8, 256>>>(shb, l2, c2);
    f2_kernel<<<dim3(16, 16), 256, SW2>>>(wt2, l2, c2, cop0, cop1);

    // LI readout over summed partials
    li_kernel<<<(BATCH * N_OUT) / 256, 256>>>(cop0, cop1, out);
}